// round 1
// baseline (speedup 1.0000x reference)
#include <cuda_runtime.h>
#include <math_constants.h>

// Problem constants
#define Bq  2
#define Lq  2048
#define Dq  1024
#define Hq  16
#define HDq 64
#define Uq  8
#define SCALE 0.03125f   // 1/sqrt(1024), exact power of two

// Scratch: context (pre-projection attention output) in [B, L, H*hd] layout
__device__ __align__(16) float g_ctx[(size_t)Bq * Lq * Dq];

// ---------------------------------------------------------------------------
// Kernel 1: scores (fp32 FMA, deterministic), streaming top-8, softmax,
//           attn_weights scatter, and fused context gather (attn @ V).
// Grid: (L/128, H, B), 128 threads. One thread = one query row.
// ---------------------------------------------------------------------------
__global__ __launch_bounds__(128) void attn_topk_kernel(
    const float* __restrict__ Q,
    const float* __restrict__ K,
    const float* __restrict__ V,
    float* __restrict__ attnw,   // d_out + B*L*D (attn_weights region), already zeroed
    int write_w)
{
    __shared__ __align__(16) float sK[32 * 64];   // 32 keys x 64 dims
    __shared__ float sW[128][Uq];
    __shared__ int   sI[128][Uq];

    const int tid = threadIdx.x;
    const int b = blockIdx.z;
    const int h = blockIdx.y;
    const int q = blockIdx.x * 128 + tid;

    // Load this thread's query vector (64 floats) into registers
    const float* qp = Q + ((size_t)(b * Lq + q)) * Dq + h * HDq;
    float4 qr[16];
#pragma unroll
    for (int i = 0; i < 16; i++) qr[i] = ((const float4*)qp)[i];

    // Running top-8 (value, index). Tie rules match jax.lax.top_k (stable sort):
    //  - new score must be STRICTLY greater than running min to enter
    //  - among equal minima, evict the LARGEST index
    float tv[Uq];
    int   ti[Uq];
#pragma unroll
    for (int i = 0; i < Uq; i++) { tv[i] = -CUDART_INF_F; ti[i] = 0; }
    float runmin = -CUDART_INF_F;

    for (int kt = 0; kt < Lq; kt += 32) {
        __syncthreads();   // previous tile fully consumed
        // Cooperative load of 32 keys x 64 dims (2048 floats = 512 float4)
        {
            const float* kbase = K + ((size_t)(b * Lq + kt)) * Dq + h * HDq;
#pragma unroll
            for (int r = 0; r < 4; r++) {
                int lin = tid + r * 128;      // float4 index
                int kk = lin >> 4;            // 16 float4 per key
                int dd = lin & 15;
                ((float4*)sK)[kk * 16 + dd] =
                    ((const float4*)(kbase + (size_t)kk * Dq))[dd];
            }
        }
        __syncthreads();

#pragma unroll 1
        for (int kk = 0; kk < 32; kk++) {
            const float4* kp = (const float4*)(sK + kk * 64);
            // Deterministic sequential fp32 dot over d = 0..63
            float s = 0.f;
#pragma unroll
            for (int i = 0; i < 16; i++) {
                float4 kv = kp[i];
                s = fmaf(qr[i].x, kv.x, s);
                s = fmaf(qr[i].y, kv.y, s);
                s = fmaf(qr[i].z, kv.z, s);
                s = fmaf(qr[i].w, kv.w, s);
            }
            if (s > runmin) {
                const int kidx = kt + kk;
                // eviction slot: min value; tie -> largest index
                int m = 0; float mv = tv[0]; int mi = ti[0];
#pragma unroll
                for (int j = 1; j < Uq; j++) {
                    bool take = (tv[j] < mv) || (tv[j] == mv && ti[j] > mi);
                    if (take) { m = j; mv = tv[j]; mi = ti[j]; }
                }
#pragma unroll
                for (int j = 0; j < Uq; j++)
                    if (j == m) { tv[j] = s; ti[j] = kidx; }
                float nm = tv[0];
#pragma unroll
                for (int j = 1; j < Uq; j++) nm = fminf(nm, tv[j]);
                runmin = nm;
            }
        }
    }

    // Softmax over the 8 kept (scaled) scores. Scale is an exact power of two,
    // so exp((s_i - s_max)*SCALE) == exp(s_i*SCALE - s_max*SCALE) exactly.
    float mx = tv[0];
#pragma unroll
    for (int j = 1; j < Uq; j++) mx = fmaxf(mx, tv[j]);
    float w[Uq]; float wsum = 0.f;
#pragma unroll
    for (int j = 0; j < Uq; j++) { w[j] = expf((tv[j] - mx) * SCALE); wsum += w[j]; }
    float inv = 1.f / wsum;
#pragma unroll
    for (int j = 0; j < Uq; j++) w[j] *= inv;

    // Scatter attn_weights (region pre-zeroed by memset)
    if (write_w) {
        float* wrow = attnw + ((size_t)((b * Hq + h) * Lq + q)) * Lq;
#pragma unroll
        for (int j = 0; j < Uq; j++) wrow[ti[j]] = w[j];
    }

    // Exchange weights/indices for the fused, coalesced V gather
#pragma unroll
    for (int j = 0; j < Uq; j++) { sW[tid][j] = w[j]; sI[tid][j] = ti[j]; }
    __syncthreads();

    // Context: each warp handles 32 queries; lane covers 2 of 64 dims (float2)
    const int lane = tid & 31;
    const int warp = tid >> 5;
    for (int qq = warp * 32; qq < warp * 32 + 32; qq++) {
        float2 acc = make_float2(0.f, 0.f);
#pragma unroll
        for (int j = 0; j < Uq; j++) {
            float wv = sW[qq][j];
            int kidx = sI[qq][j];
            const float2* vp =
                (const float2*)(V + ((size_t)(b * Lq + kidx)) * Dq + h * HDq);
            float2 vv = vp[lane];
            acc.x = fmaf(wv, vv.x, acc.x);
            acc.y = fmaf(wv, vv.y, acc.y);
        }
        int qg = blockIdx.x * 128 + qq;
        float2* cp = (float2*)(g_ctx + ((size_t)(b * Lq + qg)) * Dq + h * HDq);
        cp[lane] = acc;
    }
}

// ---------------------------------------------------------------------------
// Kernel 2: output projection  out[m,n] = sum_k ctx[m,k]*W[n,k] + bias[n]
// M = B*L = 4096, N = K = 1024.  64x64 block tile, BK=16, 256 threads,
// 4x4 register micro-tile, single-stage register prefetch.
// ---------------------------------------------------------------------------
#define PBM 64
#define PBN 64
#define PBK 16

__global__ __launch_bounds__(256) void proj_kernel(
    const float* __restrict__ Wt,    // w_out [N, K] row-major (K contiguous)
    const float* __restrict__ bias,
    float* __restrict__ Cout)        // d_out attn_out region
{
    __shared__ __align__(16) float As[PBK][PBM];
    __shared__ __align__(16) float Bs[PBK][PBN];

    const int tid = threadIdx.x;
    const int m0 = blockIdx.y * PBM;
    const int n0 = blockIdx.x * PBN;
    const int tx = tid & 15;
    const int ty = tid >> 4;
    const int Kd = Dq;

    const int lr = tid >> 2;        // 0..63  (tile row)
    const int lk = (tid & 3) * 4;   // 0,4,8,12 (k offset, float4)

    float acc[4][4];
#pragma unroll
    for (int i = 0; i < 4; i++)
#pragma unroll
        for (int j = 0; j < 4; j++) acc[i][j] = 0.f;

    float4 av = *(const float4*)(g_ctx + (size_t)(m0 + lr) * Kd + lk);
    float4 bv = *(const float4*)(Wt + (size_t)(n0 + lr) * Kd + lk);

    for (int k0 = 0; k0 < Kd; k0 += PBK) {
        As[lk + 0][lr] = av.x; As[lk + 1][lr] = av.y;
        As[lk + 2][lr] = av.z; As[lk + 3][lr] = av.w;
        Bs[lk + 0][lr] = bv.x; Bs[lk + 1][lr] = bv.y;
        Bs[lk + 2][lr] = bv.z; Bs[lk + 3][lr] = bv.w;
        __syncthreads();

        const int kn = k0 + PBK;
        float4 av2 = make_float4(0.f, 0.f, 0.f, 0.f);
        float4 bv2 = make_float4(0.f, 0.f, 0.f, 0.f);
        if (kn < Kd) {
            av2 = *(const float4*)(g_ctx + (size_t)(m0 + lr) * Kd + kn + lk);
            bv2 = *(const float4*)(Wt + (size_t)(n0 + lr) * Kd + kn + lk);
        }

#pragma unroll
        for (int k = 0; k < PBK; k++) {
            float4 a4 = *(const float4*)&As[k][ty * 4];
            float4 b4 = *(const float4*)&Bs[k][tx * 4];
            float ar[4] = {a4.x, a4.y, a4.z, a4.w};
            float br[4] = {b4.x, b4.y, b4.z, b4.w};
#pragma unroll
            for (int i = 0; i < 4; i++)
#pragma unroll
                for (int j = 0; j < 4; j++)
                    acc[i][j] = fmaf(ar[i], br[j], acc[i][j]);
        }
        __syncthreads();
        av = av2; bv = bv2;
    }

#pragma unroll
    for (int i = 0; i < 4; i++) {
        int m = m0 + ty * 4 + i;
#pragma unroll
        for (int j = 0; j < 4; j++) {
            int n = n0 + tx * 4 + j;
            Cout[(size_t)m * Dq + n] = acc[i][j] + bias[n];
        }
    }
}

// ---------------------------------------------------------------------------
extern "C" void kernel_launch(void* const* d_in, const int* in_sizes, int n_in,
                              void* d_out, int out_size)
{
    const float* Q    = (const float*)d_in[0];
    const float* K    = (const float*)d_in[1];
    const float* V    = (const float*)d_in[2];
    const float* W    = (const float*)d_in[3];
    const float* bias = (const float*)d_in[4];
    float* out = (float*)d_out;

    const size_t N_ATT = (size_t)Bq * Lq * Dq;          // 4,194,304
    const size_t N_W   = (size_t)Bq * Hq * Lq * Lq;     // 134,217,728
    const int has_w = ((size_t)out_size >= N_ATT + N_W) ? 1 : 0;
    float* attnw = out + N_ATT;

    if (has_w) {
        // attn_weights is exactly 0 off the top-8 set
        cudaMemsetAsync(attnw, 0, N_W * sizeof(float), 0);
    }

    dim3 g1(Lq / 128, Hq, Bq);
    attn_topk_kernel<<<g1, 128>>>(Q, K, V, attnw, has_w);

    dim3 g2(Dq / PBN, (Bq * Lq) / PBM);
    proj_kernel<<<g2, 256>>>(W, bias, out);
}

// round 3
// speedup vs baseline: 1.7916x; 1.7916x over previous
#include <cuda_runtime.h>
#include <math_constants.h>

// Problem constants
#define Bq  2
#define Lq  2048
#define Dq  1024
#define Hq  16
#define HDq 64
#define Uq  8
#define SCALE 0.03125f   // 1/sqrt(1024), exact power of two

typedef unsigned long long u64;

// ---- Blackwell packed f32x2 helpers (2x fp32 FMA throughput) ----
__device__ __forceinline__ u64 ffma2(u64 a, u64 b, u64 c) {
    u64 d; asm("fma.rn.f32x2 %0, %1, %2, %3;" : "=l"(d) : "l"(a), "l"(b), "l"(c));
    return d;
}
__device__ __forceinline__ u64 fadd2(u64 a, u64 b) {
    u64 d; asm("add.rn.f32x2 %0, %1, %2;" : "=l"(d) : "l"(a), "l"(b));
    return d;
}
__device__ __forceinline__ u64 pack2(float x, float y) {
    u64 r; asm("mov.b64 %0, {%1, %2};" : "=l"(r) : "f"(x), "f"(y));
    return r;
}
__device__ __forceinline__ void unpack2(u64 v, float& x, float& y) {
    asm("mov.b64 {%0, %1}, %2;" : "=f"(x), "=f"(y) : "l"(v));
}

// Scratch: context (pre-projection attention output) in [B, L, H*hd] layout
__device__ __align__(16) float g_ctx[(size_t)Bq * Lq * Dq];

// ---------------------------------------------------------------------------
// Kernel 1: scores (fp32 via packed f32x2 FMA), streaming top-8, softmax,
//           attn_weights zero-fill + scatter, fused context gather (attn @ V).
// Grid: (L/128, H, B), 128 threads. One thread = one query row.
// ---------------------------------------------------------------------------
__global__ __launch_bounds__(128) void attn_topk_kernel(
    const float* __restrict__ Q,
    const float* __restrict__ K,
    const float* __restrict__ V,
    float* __restrict__ attnw,
    int write_w)
{
    __shared__ __align__(16) float sK[32 * 64];   // 32 keys x 64 dims
    __shared__ float sW[128][Uq];
    __shared__ int   sI[128][Uq];

    const int tid = threadIdx.x;
    const int b = blockIdx.z;
    const int h = blockIdx.y;
    const int q = blockIdx.x * 128 + tid;

    // Query vector: 64 floats packed as 32 x f32x2 (64-bit lanes)
    const float* qp = Q + ((size_t)(b * Lq + q)) * Dq + h * HDq;
    u64 q2[32];
    {
        const ulonglong2* qp2 = (const ulonglong2*)qp;
#pragma unroll
        for (int i = 0; i < 16; i++) {
            ulonglong2 v = qp2[i];
            q2[2 * i] = v.x; q2[2 * i + 1] = v.y;
        }
    }

    // attnw region owned by this block: 128 contiguous rows of 2048 floats.
    // Zero-filled incrementally across the 64 key-tile iterations (hidden
    // behind the FMA-bound mainloop), then top-8 weights scattered at the end.
    float4* wz = (float4*)(attnw +
        ((size_t)((b * Hq + h) * Lq + blockIdx.x * 128)) * Lq);

    // Running top-8 (value, index). Tie rules match jax.lax.top_k:
    //  - new score must be STRICTLY greater than running min to enter
    //  - among equal minima, evict the LARGEST index
    float tv[Uq];
    int   ti[Uq];
#pragma unroll
    for (int i = 0; i < Uq; i++) { tv[i] = -CUDART_INF_F; ti[i] = 0; }
    float runmin = -CUDART_INF_F;

    for (int kt = 0; kt < Lq; kt += 32) {
        __syncthreads();   // previous tile fully consumed
        // Cooperative load of 32 keys x 64 dims (512 float4)
        {
            const float* kbase = K + ((size_t)(b * Lq + kt)) * Dq + h * HDq;
#pragma unroll
            for (int r = 0; r < 4; r++) {
                int lin = tid + r * 128;      // float4 index
                int kk = lin >> 4;            // 16 float4 per key
                int dd = lin & 15;
                ((float4*)sK)[kk * 16 + dd] =
                    ((const float4*)(kbase + (size_t)kk * Dq))[dd];
            }
        }
        // Interleaved zero-fill: 1/64th of the block's attnw region per tile
        if (write_w) {
            const float4 z = make_float4(0.f, 0.f, 0.f, 0.f);
            float4* zp = wz + (size_t)(kt >> 5) * 1024;
#pragma unroll
            for (int i = 0; i < 8; i++) zp[i * 128 + tid] = z;
        }
        __syncthreads();

#pragma unroll 1
        for (int kk = 0; kk < 32; kk++) {
            const ulonglong2* kp = (const ulonglong2*)(sK + kk * 64);
            // 32 packed FMAs, 4 independent chains of 8
            u64 a0 = 0ull, a1 = 0ull, a2 = 0ull, a3 = 0ull;
#pragma unroll
            for (int i = 0; i < 16; i += 2) {
                ulonglong2 k0 = kp[i];
                ulonglong2 k1 = kp[i + 1];
                a0 = ffma2(q2[2 * i + 0], k0.x, a0);
                a1 = ffma2(q2[2 * i + 1], k0.y, a1);
                a2 = ffma2(q2[2 * i + 2], k1.x, a2);
                a3 = ffma2(q2[2 * i + 3], k1.y, a3);
            }
            u64 a = fadd2(fadd2(a0, a1), fadd2(a2, a3));
            float slo, shi; unpack2(a, slo, shi);
            float s = slo + shi;

            if (s > runmin) {
                const int kidx = kt + kk;
                int m = 0; float mv = tv[0]; int mi = ti[0];
#pragma unroll
                for (int j = 1; j < Uq; j++) {
                    bool take = (tv[j] < mv) || (tv[j] == mv && ti[j] > mi);
                    if (take) { m = j; mv = tv[j]; mi = ti[j]; }
                }
#pragma unroll
                for (int j = 0; j < Uq; j++)
                    if (j == m) { tv[j] = s; ti[j] = kidx; }
                float nm = tv[0];
#pragma unroll
                for (int j = 1; j < Uq; j++) nm = fminf(nm, tv[j]);
                runmin = nm;
            }
        }
    }

    // Softmax over the 8 kept scores (scale is exact power of two)
    float mx = tv[0];
#pragma unroll
    for (int j = 1; j < Uq; j++) mx = fmaxf(mx, tv[j]);
    float w[Uq]; float wsum = 0.f;
#pragma unroll
    for (int j = 0; j < Uq; j++) { w[j] = expf((tv[j] - mx) * SCALE); wsum += w[j]; }
    float inv = 1.f / wsum;
#pragma unroll
    for (int j = 0; j < Uq; j++) w[j] *= inv;

    // Scatter attn_weights after all zero stores in the block have been issued
    if (write_w) {
        __syncthreads();
        float* wrow = attnw + ((size_t)((b * Hq + h) * Lq + q)) * Lq;
#pragma unroll
        for (int j = 0; j < Uq; j++) wrow[ti[j]] = w[j];
    }

    // Exchange weights/indices for the fused, coalesced V gather
#pragma unroll
    for (int j = 0; j < Uq; j++) { sW[tid][j] = w[j]; sI[tid][j] = ti[j]; }
    __syncthreads();

    // Context: each warp handles 32 queries; lane covers 2 of 64 dims
    const int lane = tid & 31;
    const int warp = tid >> 5;
    for (int qq = warp * 32; qq < warp * 32 + 32; qq++) {
        float2 acc = make_float2(0.f, 0.f);
#pragma unroll
        for (int j = 0; j < Uq; j++) {
            float wv = sW[qq][j];
            int kidx = sI[qq][j];
            const float2* vp =
                (const float2*)(V + ((size_t)(b * Lq + kidx)) * Dq + h * HDq);
            float2 vv = vp[lane];
            acc.x = fmaf(wv, vv.x, acc.x);
            acc.y = fmaf(wv, vv.y, acc.y);
        }
        int qg = blockIdx.x * 128 + qq;
        float2* cp = (float2*)(g_ctx + ((size_t)(b * Lq + qg)) * Dq + h * HDq);
        cp[lane] = acc;
    }
}

// ---------------------------------------------------------------------------
// Kernel 2: output projection  out[m,n] = sum_k ctx[m,k]*W[n,k] + bias[n]
// 64x64 block tile, BK=16, 256 threads, 4x4 micro-tile via packed f32x2
// (per-output accumulation order bit-identical to the scalar version).
// ---------------------------------------------------------------------------
#define PBM 64
#define PBN 64
#define PBK 16

__global__ __launch_bounds__(256) void proj_kernel(
    const float* __restrict__ Wt,    // w_out [N, K] row-major
    const float* __restrict__ bias,
    float* __restrict__ Cout)
{
    __shared__ __align__(16) float As[PBK][PBM];
    __shared__ __align__(16) float Bs[PBK][PBN];

    const int tid = threadIdx.x;
    const int m0 = blockIdx.y * PBM;
    const int n0 = blockIdx.x * PBN;
    const int tx = tid & 15;
    const int ty = tid >> 4;
    const int Kd = Dq;

    const int lr = tid >> 2;        // 0..63
    const int lk = (tid & 3) * 4;   // 0,4,8,12

    u64 acc[4][2];
#pragma unroll
    for (int i = 0; i < 4; i++) { acc[i][0] = 0ull; acc[i][1] = 0ull; }

    float4 av = *(const float4*)(g_ctx + (size_t)(m0 + lr) * Kd + lk);
    float4 bv = *(const float4*)(Wt + (size_t)(n0 + lr) * Kd + lk);

    for (int k0 = 0; k0 < Kd; k0 += PBK) {
        As[lk + 0][lr] = av.x; As[lk + 1][lr] = av.y;
        As[lk + 2][lr] = av.z; As[lk + 3][lr] = av.w;
        Bs[lk + 0][lr] = bv.x; Bs[lk + 1][lr] = bv.y;
        Bs[lk + 2][lr] = bv.z; Bs[lk + 3][lr] = bv.w;
        __syncthreads();

        const int kn = k0 + PBK;
        float4 av2 = make_float4(0.f, 0.f, 0.f, 0.f);
        float4 bv2 = make_float4(0.f, 0.f, 0.f, 0.f);
        if (kn < Kd) {
            av2 = *(const float4*)(g_ctx + (size_t)(m0 + lr) * Kd + kn + lk);
            bv2 = *(const float4*)(Wt + (size_t)(n0 + lr) * Kd + kn + lk);
        }

#pragma unroll
        for (int k = 0; k < PBK; k++) {
            float4 a4 = *(const float4*)&As[k][ty * 4];
            ulonglong2 b2 = *(const ulonglong2*)&Bs[k][tx * 4];
            u64 aa;
            aa = pack2(a4.x, a4.x);
            acc[0][0] = ffma2(aa, b2.x, acc[0][0]);
            acc[0][1] = ffma2(aa, b2.y, acc[0][1]);
            aa = pack2(a4.y, a4.y);
            acc[1][0] = ffma2(aa, b2.x, acc[1][0]);
            acc[1][1] = ffma2(aa, b2.y, acc[1][1]);
            aa = pack2(a4.z, a4.z);
            acc[2][0] = ffma2(aa, b2.x, acc[2][0]);
            acc[2][1] = ffma2(aa, b2.y, acc[2][1]);
            aa = pack2(a4.w, a4.w);
            acc[3][0] = ffma2(aa, b2.x, acc[3][0]);
            acc[3][1] = ffma2(aa, b2.y, acc[3][1]);
        }
        __syncthreads();
        av = av2; bv = bv2;
    }

#pragma unroll
    for (int i = 0; i < 4; i++) {
        int m = m0 + ty * 4 + i;
        float c0, c1, c2, c3;
        unpack2(acc[i][0], c0, c1);
        unpack2(acc[i][1], c2, c3);
        int n = n0 + tx * 4;
        Cout[(size_t)m * Dq + n + 0] = c0 + bias[n + 0];
        Cout[(size_t)m * Dq + n + 1] = c1 + bias[n + 1];
        Cout[(size_t)m * Dq + n + 2] = c2 + bias[n + 2];
        Cout[(size_t)m * Dq + n + 3] = c3 + bias[n + 3];
    }
}

// ---------------------------------------------------------------------------
extern "C" void kernel_launch(void* const* d_in, const int* in_sizes, int n_in,
                              void* d_out, int out_size)
{
    const float* Q    = (const float*)d_in[0];
    const float* K    = (const float*)d_in[1];
    const float* V    = (const float*)d_in[2];
    const float* W    = (const float*)d_in[3];
    const float* bias = (const float*)d_in[4];
    float* out = (float*)d_out;

    const size_t N_ATT = (size_t)Bq * Lq * Dq;          // 4,194,304
    const size_t N_W   = (size_t)Bq * Hq * Lq * Lq;     // 134,217,728
    const int has_w = ((size_t)out_size >= N_ATT + N_W) ? 1 : 0;
    float* attnw = out + N_ATT;

    dim3 g1(Lq / 128, Hq, Bq);
    attn_topk_kernel<<<g1, 128>>>(Q, K, V, attnw, has_w);

    dim3 g2(Dq / PBN, (Bq * Lq) / PBM);
    proj_kernel<<<g2, 256>>>(W, bias, out);
}

// round 4
// speedup vs baseline: 1.8092x; 1.0098x over previous
#include <cuda_runtime.h>
#include <math_constants.h>

// Problem constants
#define Bq  2
#define Lq  2048
#define Dq  1024
#define Hq  16
#define HDq 64
#define Uq  8
#define SCALE 0.03125f   // 1/sqrt(1024), exact power of two

typedef unsigned long long u64;

// ---- Blackwell packed f32x2 helpers ----
__device__ __forceinline__ u64 ffma2(u64 a, u64 b, u64 c) {
    u64 d; asm("fma.rn.f32x2 %0, %1, %2, %3;" : "=l"(d) : "l"(a), "l"(b), "l"(c));
    return d;
}
__device__ __forceinline__ u64 fadd2(u64 a, u64 b) {
    u64 d; asm("add.rn.f32x2 %0, %1, %2;" : "=l"(d) : "l"(a), "l"(b));
    return d;
}
__device__ __forceinline__ u64 pack2(float x, float y) {
    u64 r; asm("mov.b64 %0, {%1, %2};" : "=l"(r) : "f"(x), "f"(y));
    return r;
}
__device__ __forceinline__ void unpack2(u64 v, float& x, float& y) {
    asm("mov.b64 {%0, %1}, %2;" : "=f"(x), "=f"(y) : "l"(v));
}

// Scratch: context (pre-projection attention output) in [B, L, H*hd] layout
__device__ __align__(16) float g_ctx[(size_t)Bq * Lq * Dq];

// ---------------------------------------------------------------------------
// Kernel 1: scores (packed f32x2 FMA), streaming top-8, softmax,
//           attn_weights zero-fill + scatter, fused context gather.
// Grid: (L/128, H, B), 128 threads. One thread = one query row.
// K tiles double-buffered through registers: LDG for tile t+1 issued while
// computing tile t, so per-iteration exposed latency is just STS + 2 BAR.
// ---------------------------------------------------------------------------
__global__ __launch_bounds__(128) void attn_topk_kernel(
    const float* __restrict__ Q,
    const float* __restrict__ K,
    const float* __restrict__ V,
    float* __restrict__ attnw,
    int write_w)
{
    __shared__ __align__(16) float sK[32 * 64];   // 32 keys x 64 dims
    __shared__ float sW[128][Uq];
    __shared__ int   sI[128][Uq];

    const int tid = threadIdx.x;
    const int b = blockIdx.z;
    const int h = blockIdx.y;
    const int q = blockIdx.x * 128 + tid;

    // Query vector: 64 floats packed as 32 x f32x2
    const float* qp = Q + ((size_t)(b * Lq + q)) * Dq + h * HDq;
    u64 q2[32];
    {
        const ulonglong2* qp2 = (const ulonglong2*)qp;
#pragma unroll
        for (int i = 0; i < 16; i++) {
            ulonglong2 v = qp2[i];
            q2[2 * i] = v.x; q2[2 * i + 1] = v.y;
        }
    }

    // attnw region owned by this block: 128 contiguous rows of 2048 floats.
    float4* wz = (float4*)(attnw +
        ((size_t)((b * Hq + h) * Lq + blockIdx.x * 128)) * Lq);

    // Running top-8. Tie rules match jax.lax.top_k (stable):
    //  - strictly greater than running min to enter
    //  - among equal minima, evict the LARGEST index
    float tv[Uq];
    int   ti[Uq];
#pragma unroll
    for (int i = 0; i < Uq; i++) { tv[i] = -CUDART_INF_F; ti[i] = 0; }
    float runmin = -CUDART_INF_F;

    // ---- preload key tile 0 into staging registers ----
    // lin = tid + r*128 (float4 index); key kk = lin>>4, dim-quad dd = lin&15;
    // smem slot index is exactly lin.
    float4 st[4];
    {
        const float* kb = K + ((size_t)(b * Lq)) * Dq + h * HDq;
#pragma unroll
        for (int r = 0; r < 4; r++) {
            int lin = tid + r * 128;
            st[r] = ((const float4*)(kb + (size_t)(lin >> 4) * Dq))[lin & 15];
        }
    }

    for (int kt = 0; kt < Lq; kt += 32) {
        __syncthreads();   // previous tile fully consumed
        // Commit staged tile to smem
#pragma unroll
        for (int r = 0; r < 4; r++)
            ((float4*)sK)[tid + r * 128] = st[r];
        // Prefetch next tile into registers (hidden behind this tile's compute)
        if (kt + 32 < Lq) {
            const float* kb = K + ((size_t)(b * Lq + kt + 32)) * Dq + h * HDq;
#pragma unroll
            for (int r = 0; r < 4; r++) {
                int lin = tid + r * 128;
                st[r] = ((const float4*)(kb + (size_t)(lin >> 4) * Dq))[lin & 15];
            }
        }
        // Interleaved zero-fill of this block's attnw slice
        if (write_w) {
            const float4 z = make_float4(0.f, 0.f, 0.f, 0.f);
            float4* zp = wz + (size_t)(kt >> 5) * 1024;
#pragma unroll
            for (int i = 0; i < 8; i++) zp[i * 128 + tid] = z;
        }
        __syncthreads();

#pragma unroll 2
        for (int kk = 0; kk < 32; kk++) {
            const ulonglong2* kp = (const ulonglong2*)(sK + kk * 64);
            u64 a0 = 0ull, a1 = 0ull, a2 = 0ull, a3 = 0ull;
#pragma unroll
            for (int i = 0; i < 16; i += 2) {
                ulonglong2 k0 = kp[i];
                ulonglong2 k1 = kp[i + 1];
                a0 = ffma2(q2[2 * i + 0], k0.x, a0);
                a1 = ffma2(q2[2 * i + 1], k0.y, a1);
                a2 = ffma2(q2[2 * i + 2], k1.x, a2);
                a3 = ffma2(q2[2 * i + 3], k1.y, a3);
            }
            u64 a = fadd2(fadd2(a0, a1), fadd2(a2, a3));
            float slo, shi; unpack2(a, slo, shi);
            float s = slo + shi;

            if (s > runmin) {
                const int kidx = kt + kk;
                int m = 0; float mv = tv[0]; int mi = ti[0];
#pragma unroll
                for (int j = 1; j < Uq; j++) {
                    bool take = (tv[j] < mv) || (tv[j] == mv && ti[j] > mi);
                    if (take) { m = j; mv = tv[j]; mi = ti[j]; }
                }
#pragma unroll
                for (int j = 0; j < Uq; j++)
                    if (j == m) { tv[j] = s; ti[j] = kidx; }
                float nm = tv[0];
#pragma unroll
                for (int j = 1; j < Uq; j++) nm = fminf(nm, tv[j]);
                runmin = nm;
            }
        }
    }

    // Softmax over the 8 kept scores (scale is an exact power of two)
    float mx = tv[0];
#pragma unroll
    for (int j = 1; j < Uq; j++) mx = fmaxf(mx, tv[j]);
    float w[Uq]; float wsum = 0.f;
#pragma unroll
    for (int j = 0; j < Uq; j++) { w[j] = expf((tv[j] - mx) * SCALE); wsum += w[j]; }
    float inv = 1.f / wsum;
#pragma unroll
    for (int j = 0; j < Uq; j++) w[j] *= inv;

    // Scatter attn_weights after all zero stores issued
    if (write_w) {
        __syncthreads();
        float* wrow = attnw + ((size_t)((b * Hq + h) * Lq + q)) * Lq;
#pragma unroll
        for (int j = 0; j < Uq; j++) wrow[ti[j]] = w[j];
    }

    // Exchange weights/indices for the coalesced V gather
#pragma unroll
    for (int j = 0; j < Uq; j++) { sW[tid][j] = w[j]; sI[tid][j] = ti[j]; }
    __syncthreads();

    const int lane = tid & 31;
    const int warp = tid >> 5;
    for (int qq = warp * 32; qq < warp * 32 + 32; qq++) {
        float2 acc = make_float2(0.f, 0.f);
#pragma unroll
        for (int j = 0; j < Uq; j++) {
            float wv = sW[qq][j];
            int kidx = sI[qq][j];
            const float2* vp =
                (const float2*)(V + ((size_t)(b * Lq + kidx)) * Dq + h * HDq);
            float2 vv = vp[lane];
            acc.x = fmaf(wv, vv.x, acc.x);
            acc.y = fmaf(wv, vv.y, acc.y);
        }
        int qg = blockIdx.x * 128 + qq;
        float2* cp = (float2*)(g_ctx + ((size_t)(b * Lq + qg)) * Dq + h * HDq);
        cp[lane] = acc;
    }
}

// ---------------------------------------------------------------------------
// Kernel 2: output projection  out[m,n] = sum_k ctx[m,k]*W[n,k] + bias[n]
// 128x128 block tile, BK=8, 256 threads, 8x8 micro-tile via packed f32x2.
// Halves LDS bytes per MAC vs the 64x64/4x4 version and doubles FMA ILP.
// ---------------------------------------------------------------------------
#define PM 128
#define PN 128
#define PK 8
#define PPAD 132   // 528B rows: 16B-aligned, conflict-free STS/LDS

__global__ __launch_bounds__(256) void proj_kernel(
    const float* __restrict__ Wt,    // w_out [N, K] row-major
    const float* __restrict__ bias,
    float* __restrict__ Cout)
{
    __shared__ __align__(16) float As[PK][PPAD];
    __shared__ __align__(16) float Bs[PK][PPAD];

    const int tid = threadIdx.x;
    const int tx = tid & 15;         // 16 col-groups (8 cols each)
    const int ty = tid >> 4;         // 16 row-groups (8 rows each)
    const int m0 = blockIdx.y * PM;
    const int n0 = blockIdx.x * PN;

    // Global-load mapping: row lr = tid>>1 (0..127), k-quad lk = (tid&1)*4
    const int lr = tid >> 1;
    const int lk = (tid & 1) * 4;

    u64 acc[8][4];
#pragma unroll
    for (int i = 0; i < 8; i++)
#pragma unroll
        for (int p = 0; p < 4; p++) acc[i][p] = 0ull;

    const float* aptr = g_ctx + (size_t)(m0 + lr) * Dq + lk;
    const float* bptr = Wt + (size_t)(n0 + lr) * Dq + lk;
    float4 av = *(const float4*)aptr;
    float4 bv = *(const float4*)bptr;

    for (int k0 = 0; k0 < Dq; k0 += PK) {
        __syncthreads();   // previous tile fully consumed
        As[lk + 0][lr] = av.x; As[lk + 1][lr] = av.y;
        As[lk + 2][lr] = av.z; As[lk + 3][lr] = av.w;
        Bs[lk + 0][lr] = bv.x; Bs[lk + 1][lr] = bv.y;
        Bs[lk + 2][lr] = bv.z; Bs[lk + 3][lr] = bv.w;
        if (k0 + PK < Dq) {
            av = *(const float4*)(aptr + k0 + PK);
            bv = *(const float4*)(bptr + k0 + PK);
        }
        __syncthreads();

#pragma unroll
        for (int k = 0; k < PK; k++) {
            float4 a0 = *(const float4*)&As[k][ty * 8];
            float4 a1 = *(const float4*)&As[k][ty * 8 + 4];
            ulonglong2 b0 = *(const ulonglong2*)&Bs[k][tx * 8];
            ulonglong2 b1 = *(const ulonglong2*)&Bs[k][tx * 8 + 4];
            u64 aa;
            aa = pack2(a0.x, a0.x);
            acc[0][0] = ffma2(aa, b0.x, acc[0][0]);
            acc[0][1] = ffma2(aa, b0.y, acc[0][1]);
            acc[0][2] = ffma2(aa, b1.x, acc[0][2]);
            acc[0][3] = ffma2(aa, b1.y, acc[0][3]);
            aa = pack2(a0.y, a0.y);
            acc[1][0] = ffma2(aa, b0.x, acc[1][0]);
            acc[1][1] = ffma2(aa, b0.y, acc[1][1]);
            acc[1][2] = ffma2(aa, b1.x, acc[1][2]);
            acc[1][3] = ffma2(aa, b1.y, acc[1][3]);
            aa = pack2(a0.z, a0.z);
            acc[2][0] = ffma2(aa, b0.x, acc[2][0]);
            acc[2][1] = ffma2(aa, b0.y, acc[2][1]);
            acc[2][2] = ffma2(aa, b1.x, acc[2][2]);
            acc[2][3] = ffma2(aa, b1.y, acc[2][3]);
            aa = pack2(a0.w, a0.w);
            acc[3][0] = ffma2(aa, b0.x, acc[3][0]);
            acc[3][1] = ffma2(aa, b0.y, acc[3][1]);
            acc[3][2] = ffma2(aa, b1.x, acc[3][2]);
            acc[3][3] = ffma2(aa, b1.y, acc[3][3]);
            aa = pack2(a1.x, a1.x);
            acc[4][0] = ffma2(aa, b0.x, acc[4][0]);
            acc[4][1] = ffma2(aa, b0.y, acc[4][1]);
            acc[4][2] = ffma2(aa, b1.x, acc[4][2]);
            acc[4][3] = ffma2(aa, b1.y, acc[4][3]);
            aa = pack2(a1.y, a1.y);
            acc[5][0] = ffma2(aa, b0.x, acc[5][0]);
            acc[5][1] = ffma2(aa, b0.y, acc[5][1]);
            acc[5][2] = ffma2(aa, b1.x, acc[5][2]);
            acc[5][3] = ffma2(aa, b1.y, acc[5][3]);
            aa = pack2(a1.z, a1.z);
            acc[6][0] = ffma2(aa, b0.x, acc[6][0]);
            acc[6][1] = ffma2(aa, b0.y, acc[6][1]);
            acc[6][2] = ffma2(aa, b1.x, acc[6][2]);
            acc[6][3] = ffma2(aa, b1.y, acc[6][3]);
            aa = pack2(a1.w, a1.w);
            acc[7][0] = ffma2(aa, b0.x, acc[7][0]);
            acc[7][1] = ffma2(aa, b0.y, acc[7][1]);
            acc[7][2] = ffma2(aa, b1.x, acc[7][2]);
            acc[7][3] = ffma2(aa, b1.y, acc[7][3]);
        }
    }

    // Epilogue: add bias (packed) and store two 16B chunks per row
    ulonglong2 bb0 = *(const ulonglong2*)&bias[n0 + tx * 8];
    ulonglong2 bb1 = *(const ulonglong2*)&bias[n0 + tx * 8 + 4];
#pragma unroll
    for (int i = 0; i < 8; i++) {
        u64 c0 = fadd2(acc[i][0], bb0.x);
        u64 c1 = fadd2(acc[i][1], bb0.y);
        u64 c2 = fadd2(acc[i][2], bb1.x);
        u64 c3 = fadd2(acc[i][3], bb1.y);
        float* crow = Cout + (size_t)(m0 + ty * 8 + i) * Dq + n0 + tx * 8;
        ((ulonglong2*)crow)[0] = make_ulonglong2(c0, c1);
        ((ulonglong2*)crow)[1] = make_ulonglong2(c2, c3);
    }
}

// ---------------------------------------------------------------------------
extern "C" void kernel_launch(void* const* d_in, const int* in_sizes, int n_in,
                              void* d_out, int out_size)
{
    const float* Q    = (const float*)d_in[0];
    const float* K    = (const float*)d_in[1];
    const float* V    = (const float*)d_in[2];
    const float* W    = (const float*)d_in[3];
    const float* bias = (const float*)d_in[4];
    float* out = (float*)d_out;

    const size_t N_ATT = (size_t)Bq * Lq * Dq;          // 4,194,304
    const size_t N_W   = (size_t)Bq * Hq * Lq * Lq;     // 134,217,728
    const int has_w = ((size_t)out_size >= N_ATT + N_W) ? 1 : 0;
    float* attnw = out + N_ATT;

    dim3 g1(Lq / 128, Hq, Bq);
    attn_topk_kernel<<<g1, 128>>>(Q, K, V, attnw, has_w);

    dim3 g2(Dq / PN, (Bq * Lq) / PM);
    proj_kernel<<<g2, 256>>>(W, bias, out);
}